// round 16
// baseline (speedup 1.0000x reference)
#include <cuda_runtime.h>
#include <cuda_bf16.h>
#include <cstdint>

// B=2,H=16,S=2048,D=64 fp32 causal attention; d_out = out[B,H,S,D] ++ attn[B,H,S,S]
#define SEQ   2048
#define HDIM  64
#define BH    32
#define TILE  128               // q-tile rows per job
#define TK    64                // kv-tile rows per pipeline step
#define NT    (SEQ / TILE)      // 16
#define NELEM (BH * SEQ * HDIM) // 4,194,304
#define NJOBS (NT * BH)         // 512
#define NWORK 296               // persistent CTAs (2 per SM x 148 SMs)

// q pre-scale: 1/temperature * log2(e)  (epilogue uses ex2)
#define QSCALE (0.125f * 1.44269504088896341f)

// precomputed bf16 hi/lo splits (prep kernel fills these)
__device__ __align__(16) __nv_bfloat16 g_qh[NELEM];
__device__ __align__(16) __nv_bfloat16 g_ql[NELEM];
__device__ __align__(16) __nv_bfloat16 g_kh[NELEM];
__device__ __align__(16) __nv_bfloat16 g_kl[NELEM];
__device__ __align__(16) __nv_bfloat16 g_vh[NELEM];
__device__ __align__(16) __nv_bfloat16 g_vl[NELEM];
__device__ int g_ctr;           // job counter (reset by prep each launch)

// smem: 2 stages of 36864 B: KH +0 (64x144B), KL +9216, VH +18432, VL +27648
#define STG_SZ 36864
#define S_MSK  73728            // 2 x 256B (double buffered)
#define S_INV  74240            // 128 floats
#define S_JOB  74752            // 1 int
#define S_SZ   74880

// ---------------------------------------------------------------------------
__device__ __forceinline__ uint32_t smem_u32(const void* p) {
    uint32_t a;
    asm("{ .reg .u64 t; cvta.to.shared.u64 t, %1; cvt.u32.u64 %0, t; }" : "=r"(a) : "l"(p));
    return a;
}
__device__ __forceinline__ void ldsm_x4(uint32_t* r, uint32_t a) {
    asm volatile("ldmatrix.sync.aligned.m8n8.x4.shared.b16 {%0,%1,%2,%3}, [%4];"
        : "=r"(r[0]), "=r"(r[1]), "=r"(r[2]), "=r"(r[3]) : "r"(a));
}
__device__ __forceinline__ void ldsm_x4t(uint32_t* r, uint32_t a) {
    asm volatile("ldmatrix.sync.aligned.m8n8.x4.trans.shared.b16 {%0,%1,%2,%3}, [%4];"
        : "=r"(r[0]), "=r"(r[1]), "=r"(r[2]), "=r"(r[3]) : "r"(a));
}
__device__ __forceinline__ void mma16816(float* c, const uint32_t* a, const uint32_t* b) {
    asm volatile("mma.sync.aligned.m16n8k16.row.col.f32.bf16.bf16.f32 "
        "{%0,%1,%2,%3}, {%4,%5,%6,%7}, {%8,%9}, {%0,%1,%2,%3};"
        : "+f"(c[0]), "+f"(c[1]), "+f"(c[2]), "+f"(c[3])
        : "r"(a[0]), "r"(a[1]), "r"(a[2]), "r"(a[3]), "r"(b[0]), "r"(b[1]));
}
__device__ __forceinline__ void cp16(uint32_t s, const void* g) {
    asm volatile("cp.async.cg.shared.global [%0], [%1], 16;" :: "r"(s), "l"(g));
}
#define CP_COMMIT() asm volatile("cp.async.commit_group;" ::: "memory")
#define CP_WAIT0()  asm volatile("cp.async.wait_group 0;" ::: "memory")

__device__ __forceinline__ float ex2(float x) {
    float y; asm("ex2.approx.f32 %0, %1;" : "=f"(y) : "f"(x)); return y;
}
__device__ __forceinline__ void pack_split(float x, float y, uint32_t& h, uint32_t& l) {
    __nv_bfloat16 hx = __float2bfloat16(x), hy = __float2bfloat16(y);
    __nv_bfloat162 hv; hv.x = hx; hv.y = hy;
    __nv_bfloat162 lv;
    lv.x = __float2bfloat16(x - __bfloat162float(hx));
    lv.y = __float2bfloat16(y - __bfloat162float(hy));
    h = *reinterpret_cast<uint32_t*>(&hv);
    l = *reinterpret_cast<uint32_t*>(&lv);
}

// ---------------------------------------------------------------------------
// Preprocess: split q (scaled), k, v into bf16 hi/lo buffers; reset counter.
// ---------------------------------------------------------------------------
__global__ void __launch_bounds__(256)
prep(const float* __restrict__ q, const float* __restrict__ k,
     const float* __restrict__ v)
{
    if (blockIdx.x == 0 && threadIdx.x == 0) g_ctr = 0;
    size_t i = ((size_t)blockIdx.x * 256 + threadIdx.x) * 8;
    {
        float4 a = *(const float4*)(q + i), b = *(const float4*)(q + i + 4);
        a.x *= QSCALE; a.y *= QSCALE; a.z *= QSCALE; a.w *= QSCALE;
        b.x *= QSCALE; b.y *= QSCALE; b.z *= QSCALE; b.w *= QSCALE;
        uint4 h, l;
        pack_split(a.x, a.y, h.x, l.x); pack_split(a.z, a.w, h.y, l.y);
        pack_split(b.x, b.y, h.z, l.z); pack_split(b.z, b.w, h.w, l.w);
        *(uint4*)(g_qh + i) = h; *(uint4*)(g_ql + i) = l;
    }
    {
        float4 a = *(const float4*)(k + i), b = *(const float4*)(k + i + 4);
        uint4 h, l;
        pack_split(a.x, a.y, h.x, l.x); pack_split(a.z, a.w, h.y, l.y);
        pack_split(b.x, b.y, h.z, l.z); pack_split(b.z, b.w, h.w, l.w);
        *(uint4*)(g_kh + i) = h; *(uint4*)(g_kl + i) = l;
    }
    {
        float4 a = *(const float4*)(v + i), b = *(const float4*)(v + i + 4);
        uint4 h, l;
        pack_split(a.x, a.y, h.x, l.x); pack_split(a.z, a.w, h.y, l.y);
        pack_split(b.x, b.y, h.z, l.z); pack_split(b.z, b.w, h.w, l.w);
        *(uint4*)(g_vh + i) = h; *(uint4*)(g_vl + i) = l;
    }
}

// load a 64x64 bf16 tile (row = 128B contiguous) into smem, 144B row stride
#define LOADT(dstbase, gsrc) do { \
    const char* _g = (const char*)(gsrc); \
    _Pragma("unroll") \
    for (int _t = 0; _t < 2; _t++) { \
        int _i = tid + _t * 256, _r = _i >> 3, _c = _i & 7; \
        cp16((dstbase) + _r * 144 + _c * 16, _g + _r * 128 + _c * 16); \
    } \
} while (0)

// ---------------------------------------------------------------------------
// Persistent fused causal attention. 296 CTAs pull (qt,bh) jobs heavy-first.
// Per job (single pipeline pass):
//   QK^T + exp -> store unnormalized e + rowsums + PV on register e;
//   out = acc_o * invl; then embedded normalize tail: p = e * invl
//   (each warp re-reads its own rows, coalesced, L1/L2-hot).
// 256 thr = 8 warps, warp tile 16 x 64. Q fragments register-resident.
// ---------------------------------------------------------------------------
__global__ void __launch_bounds__(256, 2)
fused_attn(const int* __restrict__ mask, float* __restrict__ out,
           float* __restrict__ attn)
{
    extern __shared__ char smem[];
    const int tid = threadIdx.x, wid = tid >> 5, lane = tid & 31;
    const int g = lane >> 2, t2 = (lane & 3) << 1;
    const int m0w = wid * 16;

    float* invl = (float*)(smem + S_INV);
    int*   sjob = (int*)(smem + S_JOB);
    const uint32_t sb = smem_u32(smem);

    const uint32_t koff = (uint32_t)((((lane & 7) + ((lane >> 4) & 1) * 8) * 72
                                     + ((lane >> 3) & 1) * 8) * 2);
    const uint32_t voff = (uint32_t)(((lane & 15) * 72 + ((lane >> 4) & 1) * 8) * 2);

    for (;;) {
        // ---- grab next job ----
        if (tid == 0) *sjob = atomicAdd(&g_ctr, 1);
        __syncthreads();
        const int job = *sjob;
        __syncthreads();
        if (job >= NJOBS) break;
        const int qt = (NT - 1) - (job >> 5);   // heavy-first
        const int bh = job & 31, b = bh >> 4;
        const int nkt = 2 * qt + 2;
        const int* mrow = mask + b * SEQ;
        const size_t plane = (size_t)bh * SEQ * HDIM;
        float* attnrow = attn + (size_t)bh * SEQ * SEQ + (size_t)qt * TILE * SEQ;

        // ---- 0) zero the strictly-upper tiles (drains under compute) ----
        {
            const int zc0 = ((qt + 1) * TILE) >> 2;
            const float4 z = make_float4(0.f, 0.f, 0.f, 0.f);
            float4* zbase = (float4*)attnrow;
            for (int r = tid >> 3; r < TILE; r += 32) {
                float4* rowp = zbase + (size_t)r * (SEQ / 4);
                for (int c = zc0 + (lane & 7); c < SEQ / 4; c += 8)
                    rowp[c] = z;
            }
        }

        // ---- 1) prologue: load Q tile into stage area, hoist fragments ----
        uint32_t qfh[4][4], qfl[4][4];
        {
            const char* gq = (const char*)(g_qh + plane + (size_t)qt * TILE * HDIM);
            const char* gl = (const char*)(g_ql + plane + (size_t)qt * TILE * HDIM);
            #pragma unroll
            for (int t = 0; t < 4; t++) {
                int i = tid + t * 256, r = i >> 3, c = i & 7;
                cp16(sb + r * 144 + c * 16,         gq + r * 128 + c * 16);
                cp16(sb + 18432 + r * 144 + c * 16, gl + r * 128 + c * 16);
            }
            CP_COMMIT();
            CP_WAIT0();
            __syncthreads();
            const uint32_t qaddr = sb +
                (uint32_t)(((m0w + (lane & 15)) * 72 + ((lane >> 4) & 1) * 8) * 2);
            #pragma unroll
            for (int ks = 0; ks < 4; ks++) {
                ldsm_x4(qfh[ks], qaddr + ks * 32);
                ldsm_x4(qfl[ks], qaddr + 18432 + ks * 32);
            }
            __syncthreads();   // stage area reusable
        }

        const int ra = qt * TILE + m0w + g, rb = ra + 8;
        float rs0 = 0.f, rs1 = 0.f;
        float acc_o[8][4];
        #pragma unroll
        for (int nt = 0; nt < 8; nt++)
            #pragma unroll
            for (int jj = 0; jj < 4; jj++) acc_o[nt][jj] = 0.f;

        // ---- tile 0 loads (K + V) ----
        LOADT(sb, g_kh + plane);
        LOADT(sb + 9216, g_kl + plane);
        LOADT(sb + 18432, g_vh + plane);
        LOADT(sb + 27648, g_vl + plane);
        if (tid < 16) cp16(sb + S_MSK + tid * 16, mrow + tid * 4);
        CP_COMMIT();

        // ====== single pipeline pass: QK + exp + e store + PV ======
        for (int j = 0; j < nkt; ++j) {
            CP_WAIT0();
            __syncthreads();
            if (j + 1 < nkt) {
                const uint32_t st1 = sb + ((j + 1) & 1) * STG_SZ;
                const size_t tb = plane + (size_t)(j + 1) * TK * HDIM;
                LOADT(st1, g_kh + tb);
                LOADT(st1 + 9216, g_kl + tb);
                LOADT(st1 + 18432, g_vh + tb);
                LOADT(st1 + 27648, g_vl + tb);
                if (tid < 16)
                    cp16(sb + S_MSK + ((j + 1) & 1) * 256 + tid * 16,
                         mrow + (j + 1) * TK + tid * 4);
                CP_COMMIT();
            }
            const uint32_t stb = sb + (j & 1) * STG_SZ;
            const uint32_t kaddr = stb + koff;
            const uint32_t vaddr = stb + 18432 + voff;

            // ---- QK^T: 3-term bf16 split ----
            float acc[8][4];
            #pragma unroll
            for (int nt = 0; nt < 8; nt++)
                #pragma unroll
                for (int jj = 0; jj < 4; jj++) acc[nt][jj] = 0.f;
            #pragma unroll
            for (int ks = 0; ks < 4; ks++) {
                #pragma unroll
                for (int p = 0; p < 4; p++) {
                    uint32_t bh_[4], bl_[4];
                    uint32_t ka = kaddr + p * 2304 + ks * 32;
                    ldsm_x4(bh_, ka);
                    ldsm_x4(bl_, ka + 9216);
                    mma16816(acc[2*p],     qfh[ks], bh_);
                    mma16816(acc[2*p],     qfl[ks], bh_);
                    mma16816(acc[2*p],     qfh[ks], bl_);
                    mma16816(acc[2*p + 1], qfh[ks], bh_ + 2);
                    mma16816(acc[2*p + 1], qfl[ks], bh_ + 2);
                    mma16816(acc[2*p + 1], qfh[ks], bl_ + 2);
                }
            }

            // ---- mask + exp + store unnormalized e + rowsums ----
            const int* mskj = (const int*)(smem + S_MSK + (j & 1) * 256);
            const int kt0 = j * TK;
            const bool dtile = (j >= 2 * qt);
            float* rowa = attnrow + (size_t)(m0w + g) * SEQ + kt0;
            float* rowb = rowa + (size_t)8 * SEQ;
            #pragma unroll
            for (int nt = 0; nt < 8; nt++) {
                int lc = nt * 8 + t2, gc = kt0 + lc;
                bool k0 = mskj[lc] != 0, k1 = mskj[lc + 1] != 0;
                float e0 = (k0 && (!dtile || gc     <= ra)) ? ex2(acc[nt][0]) : 0.f;
                float e1 = (k1 && (!dtile || gc + 1 <= ra)) ? ex2(acc[nt][1]) : 0.f;
                float e2 = (k0 && (!dtile || gc     <= rb)) ? ex2(acc[nt][2]) : 0.f;
                float e3 = (k1 && (!dtile || gc + 1 <= rb)) ? ex2(acc[nt][3]) : 0.f;
                rs0 += e0 + e1; rs1 += e2 + e3;
                acc[nt][0] = e0; acc[nt][1] = e1; acc[nt][2] = e2; acc[nt][3] = e3;
                *(float2*)(rowa + lc) = make_float2(e0, e1);
                *(float2*)(rowb + lc) = make_float2(e2, e3);
            }

            // ---- P·V on unnormalized e (register repack) ----
            #pragma unroll
            for (int ks = 0; ks < 4; ks++) {
                uint32_t eh[4], el[4];
                pack_split(acc[2*ks][0],     acc[2*ks][1],     eh[0], el[0]);
                pack_split(acc[2*ks][2],     acc[2*ks][3],     eh[1], el[1]);
                pack_split(acc[2*ks + 1][0], acc[2*ks + 1][1], eh[2], el[2]);
                pack_split(acc[2*ks + 1][2], acc[2*ks + 1][3], eh[3], el[3]);
                #pragma unroll
                for (int p = 0; p < 4; p++) {
                    uint32_t vh_[4], vl_[4];
                    uint32_t va = vaddr + ks * 2304 + p * 32;
                    ldsm_x4t(vh_, va);
                    ldsm_x4t(vl_, va + 9216);
                    mma16816(acc_o[2*p],     eh, vh_);
                    mma16816(acc_o[2*p],     el, vh_);
                    mma16816(acc_o[2*p],     eh, vl_);
                    mma16816(acc_o[2*p + 1], eh, vh_ + 2);
                    mma16816(acc_o[2*p + 1], el, vh_ + 2);
                    mma16816(acc_o[2*p + 1], eh, vl_ + 2);
                }
            }
        }

        // ---- rowsum reduce -> invl ----
        rs0 += __shfl_xor_sync(0xFFFFFFFFu, rs0, 1);
        rs0 += __shfl_xor_sync(0xFFFFFFFFu, rs0, 2);
        rs1 += __shfl_xor_sync(0xFFFFFFFFu, rs1, 1);
        rs1 += __shfl_xor_sync(0xFFFFFFFFu, rs1, 2);
        if ((lane & 3) == 0) {
            invl[m0w + g]     = 1.0f / rs0;
            invl[m0w + g + 8] = 1.0f / rs1;
        }
        __syncthreads();   // invl visible; e stores visible CTA-wide
        const float il0 = invl[m0w + g], il1 = invl[m0w + g + 8];

        // ---- out = acc_o * invl ----
        float* obase = out + ((size_t)bh * SEQ + (size_t)qt * TILE) * HDIM;
        #pragma unroll
        for (int nt = 0; nt < 8; nt++) {
            int c = nt * 8 + t2;
            *(float2*)&obase[(size_t)(m0w + g) * HDIM + c] =
                make_float2(acc_o[nt][0] * il0, acc_o[nt][1] * il0);
            *(float2*)&obase[(size_t)(m0w + g + 8) * HDIM + c] =
                make_float2(acc_o[nt][2] * il1, acc_o[nt][3] * il1);
        }

        // ---- embedded normalize tail: p = e * invl (warp-own rows) ----
        {
            const int W4 = (qt + 1) * (TILE / 4);   // float4s per row holding e
            #pragma unroll 1
            for (int rr = 0; rr < 16; rr++) {
                const int r = m0w + rr;
                const float il = invl[r];
                float4* rowp = (float4*)(attnrow + (size_t)r * SEQ);
                for (int c = lane; c < W4; c += 32) {
                    float4 e4 = __ldcg(rowp + c);
                    e4.x *= il; e4.y *= il; e4.z *= il; e4.w *= il;
                    rowp[c] = e4;
                }
            }
        }
        __syncthreads();   // smem reuse safety before next job
    }
}

// ---------------------------------------------------------------------------
extern "C" void kernel_launch(void* const* d_in, const int* in_sizes, int n_in,
                              void* d_out, int out_size)
{
    const float* q    = (const float*)d_in[0];
    const float* k    = (const float*)d_in[1];
    const float* v    = (const float*)d_in[2];
    const int*   mask = (const int*)d_in[3];

    float* out  = (float*)d_out;                       // [B,H,S,D]
    float* attn = out + (size_t)BH * SEQ * HDIM;       // [B,H,S,S]

    cudaFuncSetAttribute(fused_attn, cudaFuncAttributeMaxDynamicSharedMemorySize, S_SZ);

    prep<<<NELEM / 8 / 256, 256>>>(q, k, v);
    fused_attn<<<NWORK, 256, S_SZ>>>(mask, out, attn);
}

// round 17
// speedup vs baseline: 1.1660x; 1.1660x over previous
#include <cuda_runtime.h>
#include <cuda_bf16.h>
#include <cstdint>

// B=2,H=16,S=2048,D=64 fp32 causal attention; d_out = out[B,H,S,D] ++ attn[B,H,S,S]
#define SEQ   2048
#define HDIM  64
#define BH    32
#define TILE  128               // q-tile rows per job
#define TK    64                // kv-tile rows per pipeline step
#define NT    (SEQ / TILE)      // 16
#define NELEM (BH * SEQ * HDIM) // 4,194,304
#define NJOBS (NT * BH)         // 512
#define NWORK 296               // persistent CTAs (2 per SM x 148 SMs)

// q pre-scale: 1/temperature * log2(e)  (epilogue uses ex2)
#define QSCALE (0.125f * 1.44269504088896341f)

// precomputed bf16 hi/lo splits (prep kernel fills these)
__device__ __align__(16) __nv_bfloat16 g_qh[NELEM];
__device__ __align__(16) __nv_bfloat16 g_ql[NELEM];
__device__ __align__(16) __nv_bfloat16 g_kh[NELEM];
__device__ __align__(16) __nv_bfloat16 g_kl[NELEM];
__device__ __align__(16) __nv_bfloat16 g_vh[NELEM];
__device__ __align__(16) __nv_bfloat16 g_vl[NELEM];
__device__ int g_ctr;           // job counter (reset by prep each launch)

// smem: 2 stages of 55296 B.
//  pass1 stage: KH +0 (64x144B), KL +9216
//  pass2 stage: E  +0 (128 rows x 288B fp32), VH +36864, VL +46080
#define STG_SZ 55296
#define S_MSK  110592           // 2 x 256B (double buffered)
#define S_INV  111104           // 128 floats
#define S_JOB  111616           // 1 int (job broadcast)
#define S_SZ   111744

// ---------------------------------------------------------------------------
__device__ __forceinline__ uint32_t smem_u32(const void* p) {
    uint32_t a;
    asm("{ .reg .u64 t; cvta.to.shared.u64 t, %1; cvt.u32.u64 %0, t; }" : "=r"(a) : "l"(p));
    return a;
}
__device__ __forceinline__ void ldsm_x4(uint32_t* r, uint32_t a) {
    asm volatile("ldmatrix.sync.aligned.m8n8.x4.shared.b16 {%0,%1,%2,%3}, [%4];"
        : "=r"(r[0]), "=r"(r[1]), "=r"(r[2]), "=r"(r[3]) : "r"(a));
}
__device__ __forceinline__ void ldsm_x4t(uint32_t* r, uint32_t a) {
    asm volatile("ldmatrix.sync.aligned.m8n8.x4.trans.shared.b16 {%0,%1,%2,%3}, [%4];"
        : "=r"(r[0]), "=r"(r[1]), "=r"(r[2]), "=r"(r[3]) : "r"(a));
}
__device__ __forceinline__ void mma16816(float* c, const uint32_t* a, const uint32_t* b) {
    asm volatile("mma.sync.aligned.m16n8k16.row.col.f32.bf16.bf16.f32 "
        "{%0,%1,%2,%3}, {%4,%5,%6,%7}, {%8,%9}, {%0,%1,%2,%3};"
        : "+f"(c[0]), "+f"(c[1]), "+f"(c[2]), "+f"(c[3])
        : "r"(a[0]), "r"(a[1]), "r"(a[2]), "r"(a[3]), "r"(b[0]), "r"(b[1]));
}
__device__ __forceinline__ void cp16(uint32_t s, const void* g) {
    asm volatile("cp.async.cg.shared.global [%0], [%1], 16;" :: "r"(s), "l"(g));
}
#define CP_COMMIT() asm volatile("cp.async.commit_group;" ::: "memory")
#define CP_WAIT0()  asm volatile("cp.async.wait_group 0;" ::: "memory")

__device__ __forceinline__ float ex2(float x) {
    float y; asm("ex2.approx.f32 %0, %1;" : "=f"(y) : "f"(x)); return y;
}
// streaming (evict-first) stores for data never re-read by this kernel
__device__ __forceinline__ void st_cs_f2(float* p, float2 v) {
    asm volatile("st.global.cs.v2.f32 [%0], {%1, %2};"
                 :: "l"(p), "f"(v.x), "f"(v.y) : "memory");
}
__device__ __forceinline__ void st_cs_f4(float* p, float4 v) {
    asm volatile("st.global.cs.v4.f32 [%0], {%1, %2, %3, %4};"
                 :: "l"(p), "f"(v.x), "f"(v.y), "f"(v.z), "f"(v.w) : "memory");
}
__device__ __forceinline__ void pack_split(float x, float y, uint32_t& h, uint32_t& l) {
    __nv_bfloat16 hx = __float2bfloat16(x), hy = __float2bfloat16(y);
    __nv_bfloat162 hv; hv.x = hx; hv.y = hy;
    __nv_bfloat162 lv;
    lv.x = __float2bfloat16(x - __bfloat162float(hx));
    lv.y = __float2bfloat16(y - __bfloat162float(hy));
    h = *reinterpret_cast<uint32_t*>(&hv);
    l = *reinterpret_cast<uint32_t*>(&lv);
}

// ---------------------------------------------------------------------------
// Preprocess: split q (scaled), k, v into bf16 hi/lo buffers; reset counter.
// ---------------------------------------------------------------------------
__global__ void __launch_bounds__(256)
prep(const float* __restrict__ q, const float* __restrict__ k,
     const float* __restrict__ v)
{
    if (blockIdx.x == 0 && threadIdx.x == 0) g_ctr = 0;
    size_t i = ((size_t)blockIdx.x * 256 + threadIdx.x) * 8;
    {
        float4 a = *(const float4*)(q + i), b = *(const float4*)(q + i + 4);
        a.x *= QSCALE; a.y *= QSCALE; a.z *= QSCALE; a.w *= QSCALE;
        b.x *= QSCALE; b.y *= QSCALE; b.z *= QSCALE; b.w *= QSCALE;
        uint4 h, l;
        pack_split(a.x, a.y, h.x, l.x); pack_split(a.z, a.w, h.y, l.y);
        pack_split(b.x, b.y, h.z, l.z); pack_split(b.z, b.w, h.w, l.w);
        *(uint4*)(g_qh + i) = h; *(uint4*)(g_ql + i) = l;
    }
    {
        float4 a = *(const float4*)(k + i), b = *(const float4*)(k + i + 4);
        uint4 h, l;
        pack_split(a.x, a.y, h.x, l.x); pack_split(a.z, a.w, h.y, l.y);
        pack_split(b.x, b.y, h.z, l.z); pack_split(b.z, b.w, h.w, l.w);
        *(uint4*)(g_kh + i) = h; *(uint4*)(g_kl + i) = l;
    }
    {
        float4 a = *(const float4*)(v + i), b = *(const float4*)(v + i + 4);
        uint4 h, l;
        pack_split(a.x, a.y, h.x, l.x); pack_split(a.z, a.w, h.y, l.y);
        pack_split(b.x, b.y, h.z, l.z); pack_split(b.z, b.w, h.w, l.w);
        *(uint4*)(g_vh + i) = h; *(uint4*)(g_vl + i) = l;
    }
}

// load a 64x64 bf16 tile (row = 128B contiguous) into smem, 144B row stride
#define LOADT(dstbase, gsrc) do { \
    const char* _g = (const char*)(gsrc); \
    _Pragma("unroll") \
    for (int _t = 0; _t < 2; _t++) { \
        int _i = tid + _t * 256, _r = _i >> 3, _c = _i & 7; \
        cp16((dstbase) + _r * 144 + _c * 16, _g + _r * 128 + _c * 16); \
    } \
} while (0)

// load a 128x64 fp32 e tile (gmem row stride SEQ) into smem, 288B row stride
#define LOADE(dstbase, gsrc) do { \
    const char* _g = (const char*)(gsrc); \
    _Pragma("unroll") \
    for (int _t = 0; _t < 8; _t++) { \
        int _i = tid + _t * 256, _r = _i >> 4, _c = _i & 15; \
        cp16((dstbase) + _r * 288 + _c * 16, _g + (size_t)_r * (SEQ * 4) + _c * 16); \
    } \
} while (0)

// ---------------------------------------------------------------------------
// Persistent fused causal attention. 296 CTAs pull (qt,bh) jobs heavy-first
// from an atomic counter. Per job:
//  Pass 1: QK^T + exp -> unnormalized e + rowsums (mask pre-loaded to regs).
//  Pass 2: reload e via cp.async, normalize, store p (.cs), P.V.
// 256 thr = 8 warps, warp tile 16 x 64. Q fragments register-resident.
// ---------------------------------------------------------------------------
__global__ void __launch_bounds__(256, 2)
fused_attn(const int* __restrict__ mask, float* __restrict__ out,
           float* __restrict__ attn)
{
    extern __shared__ char smem[];
    const int tid = threadIdx.x, wid = tid >> 5, lane = tid & 31;
    const int g = lane >> 2, t2 = (lane & 3) << 1;
    const int m0w = wid * 16;

    float* invl = (float*)(smem + S_INV);
    int*   sjob = (int*)(smem + S_JOB);
    const uint32_t sb = smem_u32(smem);

    const uint32_t koff = (uint32_t)((((lane & 7) + ((lane >> 4) & 1) * 8) * 72
                                     + ((lane >> 3) & 1) * 8) * 2);
    const uint32_t voff = (uint32_t)(((lane & 15) * 72 + ((lane >> 4) & 1) * 8) * 2);

    for (;;) {
        // ---- grab next job ----
        if (tid == 0) *sjob = atomicAdd(&g_ctr, 1);
        __syncthreads();
        const int job = *sjob;
        __syncthreads();
        if (job >= NJOBS) break;
        const int qt = (NT - 1) - (job >> 5);   // heavy-first
        const int bh = job & 31, b = bh >> 4;
        const int nkt = 2 * qt + 2;
        const int* mrow = mask + b * SEQ;
        const size_t plane = (size_t)bh * SEQ * HDIM;
        float* attnrow = attn + (size_t)bh * SEQ * SEQ + (size_t)qt * TILE * SEQ;

        // ---- 0) zero the strictly-upper tiles (streaming stores) ----
        {
            const int zc0 = ((qt + 1) * TILE) >> 2;
            const float4 z = make_float4(0.f, 0.f, 0.f, 0.f);
            float4* zbase = (float4*)attnrow;
            for (int r = tid >> 3; r < TILE; r += 32) {
                float4* rowp = zbase + (size_t)r * (SEQ / 4);
                for (int c = zc0 + (lane & 7); c < SEQ / 4; c += 8)
                    st_cs_f4((float*)(rowp + c), z);
            }
        }

        // ---- 1) prologue: load Q tile into stage area, hoist fragments ----
        uint32_t qfh[4][4], qfl[4][4];
        {
            const char* gq = (const char*)(g_qh + plane + (size_t)qt * TILE * HDIM);
            const char* gl = (const char*)(g_ql + plane + (size_t)qt * TILE * HDIM);
            #pragma unroll
            for (int t = 0; t < 4; t++) {
                int i = tid + t * 256, r = i >> 3, c = i & 7;
                cp16(sb + r * 144 + c * 16,         gq + r * 128 + c * 16);
                cp16(sb + 18432 + r * 144 + c * 16, gl + r * 128 + c * 16);
            }
            CP_COMMIT();
            CP_WAIT0();
            __syncthreads();
            const uint32_t qaddr = sb +
                (uint32_t)(((m0w + (lane & 15)) * 72 + ((lane >> 4) & 1) * 8) * 2);
            #pragma unroll
            for (int ks = 0; ks < 4; ks++) {
                ldsm_x4(qfh[ks], qaddr + ks * 32);
                ldsm_x4(qfl[ks], qaddr + 18432 + ks * 32);
            }
            __syncthreads();   // stage area reusable
        }

        const int ra = qt * TILE + m0w + g, rb = ra + 8;
        float rs0 = 0.f, rs1 = 0.f;

        // ====== PASS 1: QK^T + exp, store unnormalized e, rowsums =========
        LOADT(sb, g_kh + plane);
        LOADT(sb + 9216, g_kl + plane);
        if (tid < 16) cp16(sb + S_MSK + tid * 16, mrow + tid * 4);
        CP_COMMIT();

        for (int j = 0; j < nkt; ++j) {
            CP_WAIT0();
            __syncthreads();
            if (j + 1 < nkt) {
                const uint32_t st1 = sb + ((j + 1) & 1) * STG_SZ;
                const size_t tb = plane + (size_t)(j + 1) * TK * HDIM;
                LOADT(st1, g_kh + tb);
                LOADT(st1 + 9216, g_kl + tb);
                if (tid < 16)
                    cp16(sb + S_MSK + ((j + 1) & 1) * 256 + tid * 16,
                         mrow + (j + 1) * TK + tid * 4);
                CP_COMMIT();
            }
            const uint32_t kaddr = sb + (j & 1) * STG_SZ + koff;

            // preload this tile's mask bits into registers (hidden under MMAs)
            const int* mskj = (const int*)(smem + S_MSK + (j & 1) * 256);
            int mr[16];
            #pragma unroll
            for (int nt = 0; nt < 8; nt++) {
                mr[2*nt]     = mskj[nt * 8 + t2];
                mr[2*nt + 1] = mskj[nt * 8 + t2 + 1];
            }

            float acc[8][4];
            #pragma unroll
            for (int nt = 0; nt < 8; nt++)
                #pragma unroll
                for (int jj = 0; jj < 4; jj++) acc[nt][jj] = 0.f;
            #pragma unroll
            for (int ks = 0; ks < 4; ks++) {
                #pragma unroll
                for (int p = 0; p < 4; p++) {
                    uint32_t bh_[4], bl_[4];
                    uint32_t ka = kaddr + p * 2304 + ks * 32;
                    ldsm_x4(bh_, ka);
                    ldsm_x4(bl_, ka + 9216);
                    mma16816(acc[2*p],     qfh[ks], bh_);
                    mma16816(acc[2*p],     qfl[ks], bh_);
                    mma16816(acc[2*p],     qfh[ks], bl_);
                    mma16816(acc[2*p + 1], qfh[ks], bh_ + 2);
                    mma16816(acc[2*p + 1], qfl[ks], bh_ + 2);
                    mma16816(acc[2*p + 1], qfh[ks], bl_ + 2);
                }
            }

            const int kt0 = j * TK;
            const bool dtile = (j >= 2 * qt);
            float* rowa = attnrow + (size_t)(m0w + g) * SEQ + kt0;
            float* rowb = rowa + (size_t)8 * SEQ;
            #pragma unroll
            for (int nt = 0; nt < 8; nt++) {
                int lc = nt * 8 + t2, gc = kt0 + lc;
                bool k0 = mr[2*nt] != 0, k1 = mr[2*nt + 1] != 0;
                float e0 = (k0 && (!dtile || gc     <= ra)) ? ex2(acc[nt][0]) : 0.f;
                float e1 = (k1 && (!dtile || gc + 1 <= ra)) ? ex2(acc[nt][1]) : 0.f;
                float e2 = (k0 && (!dtile || gc     <= rb)) ? ex2(acc[nt][2]) : 0.f;
                float e3 = (k1 && (!dtile || gc + 1 <= rb)) ? ex2(acc[nt][3]) : 0.f;
                rs0 += e0 + e1; rs1 += e2 + e3;
                *(float2*)(rowa + lc) = make_float2(e0, e1);
                *(float2*)(rowb + lc) = make_float2(e2, e3);
            }
        }

        // ---- between passes: preload pass-2 tile 0, reduce rowsums ----
        __syncthreads();   // pass-1 smem reads done AND e stores visible CTA-wide
        LOADE(sb, attnrow);
        LOADT(sb + 36864, g_vh + plane);
        LOADT(sb + 46080, g_vl + plane);
        CP_COMMIT();

        rs0 += __shfl_xor_sync(0xFFFFFFFFu, rs0, 1);
        rs0 += __shfl_xor_sync(0xFFFFFFFFu, rs0, 2);
        rs1 += __shfl_xor_sync(0xFFFFFFFFu, rs1, 1);
        rs1 += __shfl_xor_sync(0xFFFFFFFFu, rs1, 2);
        if ((lane & 3) == 0) {
            invl[m0w + g]     = 1.0f / rs0;
            invl[m0w + g + 8] = 1.0f / rs1;
        }
        __syncthreads();
        const float il0 = invl[m0w + g], il1 = invl[m0w + g + 8];

        float acc_o[8][4];
        #pragma unroll
        for (int nt = 0; nt < 8; nt++)
            #pragma unroll
            for (int jj = 0; jj < 4; jj++) acc_o[nt][jj] = 0.f;

        // ====== PASS 2: reload e, normalize + store p (.cs), P.V ==========
        for (int j = 0; j < nkt; ++j) {
            CP_WAIT0();
            __syncthreads();
            if (j + 1 < nkt) {
                const uint32_t st1 = sb + ((j + 1) & 1) * STG_SZ;
                const size_t tb = plane + (size_t)(j + 1) * TK * HDIM;
                LOADE(st1, attnrow + (j + 1) * TK);
                LOADT(st1 + 36864, g_vh + tb);
                LOADT(st1 + 46080, g_vl + tb);
                CP_COMMIT();
            }
            const char* stb = smem + (size_t)(j & 1) * STG_SZ;
            const float* esm = (const float*)stb;
            const uint32_t vaddr = sb + (j & 1) * STG_SZ + 36864 + voff;

            const float* er0 = esm + (m0w + g) * 72;       // 288B row stride
            const float* er1 = er0 + 8 * 72;
            float* rowa = attnrow + (size_t)(m0w + g) * SEQ + j * TK;
            float* rowb = rowa + (size_t)8 * SEQ;

            #pragma unroll
            for (int ks = 0; ks < 4; ks++) {
                const int c0 = ks * 16 + t2;
                float2 p00 = *(const float2*)(er0 + c0);
                float2 p10 = *(const float2*)(er1 + c0);
                float2 p01 = *(const float2*)(er0 + c0 + 8);
                float2 p11 = *(const float2*)(er1 + c0 + 8);
                p00.x *= il0; p00.y *= il0; p01.x *= il0; p01.y *= il0;
                p10.x *= il1; p10.y *= il1; p11.x *= il1; p11.y *= il1;
                st_cs_f2(rowa + c0,     p00);
                st_cs_f2(rowa + c0 + 8, p01);
                st_cs_f2(rowb + c0,     p10);
                st_cs_f2(rowb + c0 + 8, p11);

                uint32_t eh[4], el[4];
                pack_split(p00.x, p00.y, eh[0], el[0]);
                pack_split(p10.x, p10.y, eh[1], el[1]);
                pack_split(p01.x, p01.y, eh[2], el[2]);
                pack_split(p11.x, p11.y, eh[3], el[3]);
                #pragma unroll
                for (int p = 0; p < 4; p++) {
                    uint32_t vh_[4], vl_[4];
                    uint32_t va = vaddr + ks * 2304 + p * 32;
                    ldsm_x4t(vh_, va);
                    ldsm_x4t(vl_, va + 9216);
                    mma16816(acc_o[2*p],     eh, vh_);
                    mma16816(acc_o[2*p],     el, vh_);
                    mma16816(acc_o[2*p],     eh, vl_);
                    mma16816(acc_o[2*p + 1], eh, vh_ + 2);
                    mma16816(acc_o[2*p + 1], el, vh_ + 2);
                    mma16816(acc_o[2*p + 1], eh, vl_ + 2);
                }
            }
        }

        // ---- out = acc_o (already normalized) ----
        float* obase = out + ((size_t)bh * SEQ + (size_t)qt * TILE) * HDIM;
        #pragma unroll
        for (int nt = 0; nt < 8; nt++) {
            int c = nt * 8 + t2;
            *(float2*)&obase[(size_t)(m0w + g) * HDIM + c] =
                make_float2(acc_o[nt][0], acc_o[nt][1]);
            *(float2*)&obase[(size_t)(m0w + g + 8) * HDIM + c] =
                make_float2(acc_o[nt][2], acc_o[nt][3]);
        }
        __syncthreads();   // smem reuse safety before next job
    }
}

// ---------------------------------------------------------------------------
extern "C" void kernel_launch(void* const* d_in, const int* in_sizes, int n_in,
                              void* d_out, int out_size)
{
    const float* q    = (const float*)d_in[0];
    const float* k    = (const float*)d_in[1];
    const float* v    = (const float*)d_in[2];
    const int*   mask = (const int*)d_in[3];

    float* out  = (float*)d_out;                       // [B,H,S,D]
    float* attn = out + (size_t)BH * SEQ * HDIM;       // [B,H,S,S]

    cudaFuncSetAttribute(fused_attn, cudaFuncAttributeMaxDynamicSharedMemorySize, S_SZ);

    prep<<<NELEM / 8 / 256, 256>>>(q, k, v);
    fused_attn<<<NWORK, 256, S_SZ>>>(mask, out, attn);
}